// round 1
// baseline (speedup 1.0000x reference)
#include <cuda_runtime.h>

typedef unsigned long long ULL;

__device__ __forceinline__ ULL pack2(float a, float b) {
    ULL r; asm("mov.b64 %0,{%1,%2};" : "=l"(r) : "f"(a), "f"(b)); return r;
}
__device__ __forceinline__ float2 unpack2(ULL a) {
    float lo, hi; asm("mov.b64 {%0,%1},%2;" : "=f"(lo), "=f"(hi) : "l"(a));
    return make_float2(lo, hi);
}
__device__ __forceinline__ ULL ffma2(ULL a, ULL b, ULL c) {
    ULL r; asm("fma.rn.f32x2 %0,%1,%2,%3;" : "=l"(r) : "l"(a), "l"(b), "l"(c)); return r;
}
__device__ __forceinline__ ULL fmul2(ULL a, ULL b) {
    ULL r; asm("mul.rn.f32x2 %0,%1,%2;" : "=l"(r) : "l"(a), "l"(b)); return r;
}
__device__ __forceinline__ ULL fadd2(ULL a, ULL b) {
    ULL r; asm("add.rn.f32x2 %0,%1,%2;" : "=l"(r) : "l"(a), "l"(b)); return r;
}

// Geometry
//  window: 8x8 = 64 tokens, EMBED=96, NH=6, CH=16, SCALE=0.25
// Shared memory layout (in floats). All region starts are 16B aligned.
constexpr int OFF_W  = 0;                  // proj_w, 96*96 = 9216 (row-major [o][e])
constexpr int OFF_Q  = OFF_W  + 9216;      // 64*96 = 6144
constexpr int OFF_K  = OFF_Q  + 6144;
constexpr int OFF_V  = OFF_K  + 6144;
constexpr int OFF_X  = OFF_V  + 6144;      // 64*100 = 6400 (stride 100: 16B-aligned rows, low conflicts)
constexpr int OFF_B  = OFF_X  + 6400;      // bias table 225*6 = 1350, pad to 1352
constexpr int OFF_G  = OFF_B  + 1352;      // gamma 96
constexpr int OFF_BE = OFF_G  + 96;        // beta 96
constexpr int OFF_PB = OFF_BE + 96;        // proj bias 96
constexpr int OFF_MU = OFF_PB + 96;        // 64
constexpr int OFF_RS = OFF_MU + 64;        // 64
constexpr int SMEM_FLOATS = OFF_RS + 64;   // 35816 floats = 143264 B

__global__ __launch_bounds__(384, 1)
void win_attn_kernel(const float* __restrict__ Qg, const float* __restrict__ Kg,
                     const float* __restrict__ Vg, const float* __restrict__ Mg,
                     const float* __restrict__ Bt, const float* __restrict__ Gm,
                     const float* __restrict__ Be, const float* __restrict__ Wp,
                     const float* __restrict__ Pb, float* __restrict__ Og)
{
    extern __shared__ float sm[];
    const int t = threadIdx.x;
    const int w = blockIdx.x;

    // ---- Stage inputs into SMEM (coalesced float4) ----
    {
        float4* dW = (float4*)(sm + OFF_W);
        const float4* gW = (const float4*)Wp;
        for (int idx = t; idx < 2304; idx += 384) dW[idx] = gW[idx];

        const long base = (long)w * 6144;
        float4* dQ = (float4*)(sm + OFF_Q); const float4* gQ = (const float4*)(Qg + base);
        float4* dK = (float4*)(sm + OFF_K); const float4* gK = (const float4*)(Kg + base);
        float4* dV = (float4*)(sm + OFF_V); const float4* gV = (const float4*)(Vg + base);
        for (int idx = t; idx < 1536; idx += 384) {
            dQ[idx] = gQ[idx]; dK[idx] = gK[idx]; dV[idx] = gV[idx];
        }
        for (int idx = t; idx < 1350; idx += 384) sm[OFF_B + idx] = Bt[idx];
        if (t < 96) {
            sm[OFF_G  + t] = Gm[t];
            sm[OFF_BE + t] = Be[t];
            sm[OFF_PB + t] = Pb[t];
        }
    }
    __syncthreads();

    // ---- Attention: thread = (head h, row i). Warp-uniform h -> all K/V smem reads broadcast.
    const int h = t >> 6;      // 0..5
    const int i = t & 63;      // 0..63

    ULL qd[8];   // scaled q row, packed f32x2 pairs
    {
        const ULL* qr = (const ULL*)(sm + OFF_Q + i * 96 + h * 16);
        const ULL sc = pack2(0.25f, 0.25f);
        #pragma unroll
        for (int c = 0; c < 8; c++) qd[c] = fmul2(qr[c], sc);
    }

    float s[64];
    #pragma unroll
    for (int j = 0; j < 64; j++) {
        const ULL* kr = (const ULL*)(sm + OFF_K + j * 96 + h * 16);
        ULL a = 0ull;  // {+0.f, +0.f}
        #pragma unroll
        for (int c = 0; c < 8; c++) a = ffma2(qd[c], kr[c], a);
        float2 f = unpack2(a);
        s[j] = f.x + f.y;
    }

    // relative-position bias (computed index) + per-window mask + running max
    const int yi = i >> 3, xi = i & 7;
    const float* mrow = Mg + ((long)w * 64 + i) * 64;
    float mx = -3.0e38f;
    #pragma unroll
    for (int j4 = 0; j4 < 16; j4++) {
        const float4 m4 = __ldg((const float4*)mrow + j4);
        #pragma unroll
        for (int u = 0; u < 4; u++) {
            const int j = j4 * 4 + u;
            const float mv = (&m4.x)[u];
            const int dy = yi - (j >> 3) + 7;
            const int dx = xi - (j & 7) + 7;
            s[j] += sm[OFF_B + (dy * 15 + dx) * 6 + h] + mv;
            mx = fmaxf(mx, s[j]);
        }
    }

    // softmax in registers
    float ssum = 0.0f;
    #pragma unroll
    for (int j = 0; j < 64; j++) {
        const float e = __expf(s[j] - mx);
        s[j] = e;
        ssum += e;
    }
    const float inv = 1.0f / ssum;

    // out = attn @ V + q_scaled  (residual seeds the accumulator)
    ULL acc[8];
    #pragma unroll
    for (int c = 0; c < 8; c++) acc[c] = qd[c];
    #pragma unroll
    for (int j = 0; j < 64; j++) {
        const float p = s[j] * inv;
        const ULL p2 = pack2(p, p);
        const ULL* vr = (const ULL*)(sm + OFF_V + j * 96 + h * 16);
        #pragma unroll
        for (int c = 0; c < 8; c++) acc[c] = ffma2(p2, vr[c], acc[c]);
    }
    {
        // x[token][h*16+c]  (token-major, heads concatenated) with stride 100
        ULL* xr = (ULL*)(sm + OFF_X + i * 100 + h * 16);
        #pragma unroll
        for (int c = 0; c < 8; c++) xr[c] = acc[c];
    }
    __syncthreads();

    // ---- LayerNorm stats (64 threads, one token each) ----
    if (t < 64) {
        const float* xr = sm + OFF_X + t * 100;
        float s1 = 0.0f, s2 = 0.0f;
        #pragma unroll
        for (int e = 0; e < 96; e++) { const float v = xr[e]; s1 += v; s2 += v * v; }
        const float mu  = s1 * (1.0f / 96.0f);
        const float var = s2 * (1.0f / 96.0f) - mu * mu;
        sm[OFF_MU + t] = mu;
        sm[OFF_RS + t] = rsqrtf(var + 1e-5f);
    }
    __syncthreads();

    // ---- Normalize in place: (x - mu) * rstd * gamma + beta ----
    #pragma unroll
    for (int k = 0; k < 16; k++) {
        const int idx = t + k * 384;       // 0..6143
        const int token = idx / 96;
        const int e = idx - token * 96;
        const float mu = sm[OFF_MU + token];
        const float rs = sm[OFF_RS + token];
        const float v = sm[OFF_X + token * 100 + e];
        sm[OFF_X + token * 100 + e] = (v - mu) * rs * sm[OFF_G + e] + sm[OFF_BE + e];
    }
    __syncthreads();

    // ---- Projection: y[token][o] = b[o] + sum_e x[e] * W[o][e]
    // thread = (token = t&63, output group og = t>>6 covering 16 outputs)
    {
        const int token = t & 63;
        const int og = t >> 6;
        const int o0 = og * 16;

        // cache normalized x row in 48 packed pairs (24 LDS.128)
        ULL x2[48];
        const ulonglong2* xr = (const ulonglong2*)(sm + OFF_X + token * 100);
        #pragma unroll
        for (int e4 = 0; e4 < 24; e4++) {
            const ulonglong2 v = xr[e4];
            x2[2 * e4]     = v.x;
            x2[2 * e4 + 1] = v.y;
        }

        float r[16];
        #pragma unroll
        for (int k = 0; k < 16; k++) {
            const int o = o0 + k;
            const ulonglong2* wr = (const ulonglong2*)(sm + OFF_W + o * 96); // warp-broadcast
            ULL a0 = 0ull, a1 = 0ull;
            #pragma unroll
            for (int e4 = 0; e4 < 24; e4++) {
                const ulonglong2 wv = wr[e4];
                a0 = ffma2(x2[2 * e4],     wv.x, a0);
                a1 = ffma2(x2[2 * e4 + 1], wv.y, a1);
            }
            const float2 f = unpack2(fadd2(a0, a1));
            r[k] = f.x + f.y + sm[OFF_PB + o];
        }

        float4* orow = (float4*)(Og + ((long)w * 64 + token) * 96 + o0);
        #pragma unroll
        for (int k4 = 0; k4 < 4; k4++)
            orow[k4] = make_float4(r[k4 * 4], r[k4 * 4 + 1], r[k4 * 4 + 2], r[k4 * 4 + 3]);
    }
}

extern "C" void kernel_launch(void* const* d_in, const int* in_sizes, int n_in,
                              void* d_out, int out_size)
{
    const float* Q  = (const float*)d_in[0];
    const float* K  = (const float*)d_in[1];
    const float* V  = (const float*)d_in[2];
    const float* M  = (const float*)d_in[3];
    const float* Bt = (const float*)d_in[4];
    const float* Gm = (const float*)d_in[5];
    const float* Be = (const float*)d_in[6];
    const float* Wp = (const float*)d_in[7];
    const float* Pb = (const float*)d_in[8];
    float* O = (float*)d_out;

    const int nw = in_sizes[0] / (64 * 96);   // windows

    cudaFuncSetAttribute(win_attn_kernel,
                         cudaFuncAttributeMaxDynamicSharedMemorySize,
                         SMEM_FLOATS * (int)sizeof(float));

    win_attn_kernel<<<nw, 384, SMEM_FLOATS * (int)sizeof(float)>>>(
        Q, K, V, M, Bt, Gm, Be, Wp, Pb, O);
}